// round 13
// baseline (speedup 1.0000x reference)
#include <cuda_runtime.h>
#include <math.h>

// Problem constants
#define NN 100000
#define EE 1600000
#define ET (EE + NN)      // edges + self loops
#define FF 128            // feature dim everywhere (IN = H*C = 128)
#define HH 4
#define CC 32
#define NEG_SLOPE 0.2f
#define SCAN_B 98         // 98 * 1024 >= NN

// ----------------------------------------------------------------------------
// Scratch (device globals; no allocations allowed)
// ----------------------------------------------------------------------------
__device__ float g_h[(size_t)NN * FF];     // transformed features of current layer
__device__ float g_feat[(size_t)NN * FF];  // input features for layers 1,2
__device__ __align__(16) float g_es[NN * HH];
__device__ __align__(16) float g_ed[NN * HH];
__device__ int   g_off[NN + 1];
__device__ int   g_cur[NN];                // counts, then cursors
__device__ int   g_csr[ET];                // src node per CSR slot (grouped by dst)
__device__ int   g_bsum[SCAN_B];
__device__ int   g_is64;                   // 1 if edge_index is int64, 0 if int32

// ----------------------------------------------------------------------------
// Edge index dtype probe (JAX may give int32 or int64)
// ----------------------------------------------------------------------------
__global__ void k_detect(const int* __restrict__ ei32) {
    if (threadIdx.x == 0) {
        int all0 = 1;
        for (int j = 1; j < 256; j += 2)
            if (ei32[j] != 0) { all0 = 0; break; }
        g_is64 = all0;
    }
}

__device__ __forceinline__ int load_edge(const void* ei, size_t idx) {
    if (g_is64) return (int)((const long long*)ei)[idx];
    return ((const int*)ei)[idx];
}

// ----------------------------------------------------------------------------
// CSR build: counting sort by dst
// ----------------------------------------------------------------------------
__global__ void k_init_counts() {
    int n = blockIdx.x * blockDim.x + threadIdx.x;
    if (n < NN) g_cur[n] = 1;  // self loop
}

__global__ void k_count(const void* __restrict__ ei) {
    int i = blockIdx.x * blockDim.x + threadIdx.x;
    if (i < EE) {
        int d = load_edge(ei, (size_t)EE + i);
        atomicAdd(&g_cur[d], 1);
    }
}

__global__ void __launch_bounds__(1024) k_blocksum() {
    __shared__ int sh[32];
    int t = threadIdx.x;
    int g = blockIdx.x * 1024 + t;
    int c = (g < NN) ? g_cur[g] : 0;
#pragma unroll
    for (int o = 16; o; o >>= 1) c += __shfl_xor_sync(0xffffffffu, c, o);
    if ((t & 31) == 0) sh[t >> 5] = c;
    __syncthreads();
    if (t < 32) {
        int v = sh[t];
#pragma unroll
        for (int o = 16; o; o >>= 1) v += __shfl_xor_sync(0xffffffffu, v, o);
        if (t == 0) g_bsum[blockIdx.x] = v;
    }
}

__global__ void k_scan_top() {
    __shared__ int sh[SCAN_B];
    int t = threadIdx.x;
    if (t < SCAN_B) sh[t] = g_bsum[t];
    __syncthreads();
    if (t == 0) {
        int run = 0;
        for (int i = 0; i < SCAN_B; i++) { int c = sh[i]; sh[i] = run; run += c; }
    }
    __syncthreads();
    if (t < SCAN_B) g_bsum[t] = sh[t];
}

__global__ void __launch_bounds__(1024) k_scan_final() {
    __shared__ int sh[1024];
    int t = threadIdx.x;
    int g = blockIdx.x * 1024 + t;
    int c = (g < NN) ? g_cur[g] : 0;
    sh[t] = c;
    __syncthreads();
#pragma unroll
    for (int off = 1; off < 1024; off <<= 1) {
        int v = (t >= off) ? sh[t - off] : 0;
        __syncthreads();
        sh[t] += v;
        __syncthreads();
    }
    int excl = sh[t] - c + g_bsum[blockIdx.x];
    if (g < NN) {
        g_off[g] = excl;
        g_cur[g] = excl;
    }
    if (g == 0) g_off[NN] = ET;
}

__global__ void k_scatter(const void* __restrict__ ei) {
    int i = blockIdx.x * blockDim.x + threadIdx.x;
    if (i >= ET) return;
    int s, d;
    if (i < EE) {
        s = load_edge(ei, i);
        d = load_edge(ei, (size_t)EE + i);
    } else {
        s = d = i - EE;  // self loop
    }
    int p = atomicAdd(&g_cur[d], 1);
    g_csr[p] = s;
}

// ----------------------------------------------------------------------------
// GEMM: g_h = X[N,128] @ W[128,128], fused attention epilogue.
// 128-row x 128-col tile, k-tiled by 32; 256 threads; thread = 8 rows x 8 cols
// (raises FMA/LDS issue ratio from 32/9 to 64/10 vs the 8x4 tile).
// cg = tid & 15 -> cols 8cg..8cg+7 (head cg>>2); rg = tid >> 4 -> rows 8rg...
// ----------------------------------------------------------------------------
__global__ void __launch_bounds__(256, 2) k_gemm(const float* __restrict__ Xext,
                                                 const float* __restrict__ W,
                                                 const float* __restrict__ a_src,
                                                 const float* __restrict__ a_dst,
                                                 int use_gfeat) {
    const float* X = use_gfeat ? g_feat : Xext;
    __shared__ float sX[128 * 32];
    __shared__ float sW[32 * 128];
    float4* sX4 = (float4*)sX;
    float4* sW4 = (float4*)sW;

    int tid = threadIdx.x;
    int row0 = blockIdx.x * 128;
    int cg = tid & 15;   // col group: cols 8cg..8cg+7
    int rg = tid >> 4;   // row group: rows 8rg..8rg+7

    float acc[8][8] = {};

    for (int kt = 0; kt < 4; kt++) {
        int k0 = kt * 32;
        // X tile: 128 x 32 floats = 1024 float4; 4 per thread
#pragma unroll
        for (int j = 0; j < 4; j++) {
            int idx = tid + 256 * j;
            int r = idx >> 3, c4 = idx & 7;
            float4 v = make_float4(0.f, 0.f, 0.f, 0.f);
            int gr = row0 + r;
            if (gr < NN) v = *(const float4*)(X + (size_t)gr * FF + k0 + 4 * c4);
            sX4[idx] = v;
        }
        // W tile: 32 x 128 floats = 1024 float4; 4 per thread
#pragma unroll
        for (int j = 0; j < 4; j++) {
            int idx = tid + 256 * j;
            int r = idx >> 5, c4 = idx & 31;
            sW4[idx] = *(const float4*)(W + (size_t)(k0 + r) * FF + 4 * c4);
        }
        __syncthreads();
#pragma unroll
        for (int kk = 0; kk < 32; kk++) {
            float4 w0 = sW4[kk * 32 + 2 * cg];
            float4 w1 = sW4[kk * 32 + 2 * cg + 1];
#pragma unroll
            for (int i = 0; i < 8; i++) {
                float xv = sX[(rg * 8 + i) * 32 + kk];
                acc[i][0] += xv * w0.x;
                acc[i][1] += xv * w0.y;
                acc[i][2] += xv * w0.z;
                acc[i][3] += xv * w0.w;
                acc[i][4] += xv * w1.x;
                acc[i][5] += xv * w1.y;
                acc[i][6] += xv * w1.z;
                acc[i][7] += xv * w1.w;
            }
        }
        __syncthreads();
    }

    // Attention epilogue. Thread's 8 cols all lie in head cg>>2. The 4 threads
    // covering a (row, head) pair are contiguous lanes -> 2-step shfl reduce.
    float4 as0 = *(const float4*)(a_src + 8 * cg);
    float4 as1 = *(const float4*)(a_src + 8 * cg + 4);
    float4 ad0 = *(const float4*)(a_dst + 8 * cg);
    float4 ad1 = *(const float4*)(a_dst + 8 * cg + 4);
    int head = cg >> 2;

#pragma unroll
    for (int i = 0; i < 8; i++) {
        int gr = row0 + rg * 8 + i;
        float vs = acc[i][0] * as0.x + acc[i][1] * as0.y + acc[i][2] * as0.z + acc[i][3] * as0.w
                 + acc[i][4] * as1.x + acc[i][5] * as1.y + acc[i][6] * as1.z + acc[i][7] * as1.w;
        float vd = acc[i][0] * ad0.x + acc[i][1] * ad0.y + acc[i][2] * ad0.z + acc[i][3] * ad0.w
                 + acc[i][4] * ad1.x + acc[i][5] * ad1.y + acc[i][6] * ad1.z + acc[i][7] * ad1.w;
#pragma unroll
        for (int o = 2; o; o >>= 1) {
            vs += __shfl_xor_sync(0xffffffffu, vs, o);
            vd += __shfl_xor_sync(0xffffffffu, vd, o);
        }
        if (gr < NN) {
            *(float4*)(g_h + (size_t)gr * FF + 8 * cg) =
                make_float4(acc[i][0], acc[i][1], acc[i][2], acc[i][3]);
            *(float4*)(g_h + (size_t)gr * FF + 8 * cg + 4) =
                make_float4(acc[i][4], acc[i][5], acc[i][6], acc[i][7]);
            if ((cg & 3) == 0) {
                g_es[gr * HH + head] = vs;
                g_ed[gr * HH + head] = vd;
            }
        }
    }
}

// ----------------------------------------------------------------------------
// Edge phase: WARP per dst node. Lane l owns channels 4l..4l+3 (head l>>3).
// Per edge: 1 LDG.128 gather + 2 LDS + 4 FFMA.
// ----------------------------------------------------------------------------
__global__ void __launch_bounds__(128) k_edge(const float* __restrict__ bias,
                                              float* __restrict__ out_ext,
                                              int last) {
    __shared__ int   s_src[4][32];
    __shared__ float s_w[4][32][4];

    int wid = threadIdx.x >> 5;
    int lane = threadIdx.x & 31;
    int node = blockIdx.x * 4 + wid;   // NN = 4 * 25000 exactly
    int hd = lane >> 3;

    int beg = g_off[node];
    int end = g_off[node + 1];
    float4 ed4 = *(const float4*)(g_ed + node * HH);

    float4 acc = make_float4(0.f, 0.f, 0.f, 0.f);
    float wsum = 0.f;

    for (int base = beg; base < end; base += 32) {
        int m = min(32, end - base);
        if (lane < m) {
            int s = g_csr[base + lane];
            s_src[wid][lane] = s;
            float4 e = *(const float4*)(g_es + s * HH);
            float z0 = e.x + ed4.x; z0 = (z0 > 0.f) ? z0 : NEG_SLOPE * z0;
            float z1 = e.y + ed4.y; z1 = (z1 > 0.f) ? z1 : NEG_SLOPE * z1;
            float z2 = e.z + ed4.z; z2 = (z2 > 0.f) ? z2 : NEG_SLOPE * z2;
            float z3 = e.w + ed4.w; z3 = (z3 > 0.f) ? z3 : NEG_SLOPE * z3;
            s_w[wid][lane][0] = __expf(z0);
            s_w[wid][lane][1] = __expf(z1);
            s_w[wid][lane][2] = __expf(z2);
            s_w[wid][lane][3] = __expf(z3);
        }
        __syncwarp();
#pragma unroll 4
        for (int j = 0; j < m; j++) {
            float w = s_w[wid][j][hd];
            int s = s_src[wid][j];
            float4 f = *(const float4*)(g_h + (size_t)s * FF + 4 * lane);
            acc.x += w * f.x;
            acc.y += w * f.y;
            acc.z += w * f.z;
            acc.w += w * f.w;
            wsum += w;
        }
        __syncwarp();
    }

    float inv = 1.f / wsum;
    float4 b4 = *(const float4*)(bias + 4 * lane);
    float4 o;
    o.x = acc.x * inv + b4.x;
    o.y = acc.y * inv + b4.y;
    o.z = acc.z * inv + b4.z;
    o.w = acc.w * inv + b4.w;
    if (!last) {
        o.x = (o.x > 0.f) ? o.x : (__expf(o.x) - 1.f);
        o.y = (o.y > 0.f) ? o.y : (__expf(o.y) - 1.f);
        o.z = (o.z > 0.f) ? o.z : (__expf(o.z) - 1.f);
        o.w = (o.w > 0.f) ? o.w : (__expf(o.w) - 1.f);
    }
    float* out = last ? out_ext : g_feat;
    *(float4*)(out + (size_t)node * FF + 4 * lane) = o;
}

// ----------------------------------------------------------------------------
// Launch. GEMM layer 0 stays at launch index 3 so ncu profiles it.
// ----------------------------------------------------------------------------
extern "C" void kernel_launch(void* const* d_in, const int* in_sizes, int n_in,
                              void* d_out, int out_size) {
    const float* x  = (const float*)d_in[0];
    const void*  ei = d_in[1];
    const float* W[3]  = {(const float*)d_in[2], (const float*)d_in[6],  (const float*)d_in[10]};
    const float* AS[3] = {(const float*)d_in[3], (const float*)d_in[7],  (const float*)d_in[11]};
    const float* AD[3] = {(const float*)d_in[4], (const float*)d_in[8],  (const float*)d_in[12]};
    const float* B[3]  = {(const float*)d_in[5], (const float*)d_in[9],  (const float*)d_in[13]};
    float* out = (float*)d_out;

    const int gemm_blocks = (NN + 127) / 128;

    k_detect<<<1, 32>>>((const int*)ei);                       // 0
    k_init_counts<<<(NN + 255) / 256, 256>>>();                // 1
    k_count<<<(EE + 255) / 256, 256>>>(ei);                    // 2
    k_gemm<<<gemm_blocks, 256>>>(x, W[0], AS[0], AD[0], 0);    // 3  <- profiled
    k_blocksum<<<SCAN_B, 1024>>>();                            // 4
    k_scan_top<<<1, 128>>>();                                  // 5
    k_scan_final<<<SCAN_B, 1024>>>();                          // 6
    k_scatter<<<(ET + 255) / 256, 256>>>(ei);                  // 7

    k_edge<<<NN / 4, 128>>>(B[0], out, 0);
    for (int L = 1; L < 3; L++) {
        k_gemm<<<gemm_blocks, 256>>>(x, W[L], AS[L], AD[L], 1);
        k_edge<<<NN / 4, 128>>>(B[L], out, L == 2 ? 1 : 0);
    }
}